// round 2
// baseline (speedup 1.0000x reference)
#include <cuda_runtime.h>

#define ED 12
#define FF 24
#define SQ 8
#define VO 128
#define BPB 32            // batch elements per block
#define NTHREADS 256
#define KST 13            // padded per-token stride for K/V in smem (bank-conflict-free)

typedef unsigned long long u64;

__device__ __forceinline__ u64 pack2(float lo, float hi) {
    u64 r;
    asm("mov.b64 %0, {%1, %2};" : "=l"(r) : "f"(lo), "f"(hi));
    return r;
}
__device__ __forceinline__ void unpack2(u64 u, float& lo, float& hi) {
    asm("mov.b64 {%0, %1}, %2;" : "=f"(lo), "=f"(hi) : "l"(u));
}
__device__ __forceinline__ u64 fma2(u64 a, u64 b, u64 c) {
    u64 r;
    asm("fma.rn.f32x2 %0, %1, %2, %3;" : "=l"(r) : "l"(a), "l"(b), "l"(c));
    return r;
}
// horizontal reduce of a packed accumulator
__device__ __forceinline__ float hsum2(u64 u) {
    float lo, hi; unpack2(u, lo, hi); return lo + hi;
}

__global__ __launch_bounds__(NTHREADS)
void tiny_tf_kernel(const int* __restrict__ x,
                    const float* __restrict__ embed,
                    const float* __restrict__ pos,
                    const float* __restrict__ Wq, const float* __restrict__ bq,
                    const float* __restrict__ Wk, const float* __restrict__ bk,
                    const float* __restrict__ Wv, const float* __restrict__ bv,
                    const float* __restrict__ Wo, const float* __restrict__ bo,
                    const float* __restrict__ W1, const float* __restrict__ b1,
                    const float* __restrict__ W2, const float* __restrict__ b2,
                    const float* __restrict__ blm,
                    float* __restrict__ out)
{
    __shared__ __align__(16) float sE[VO * ED];        // 6144 B
    __shared__ __align__(16) float sPos[SQ * ED];
    __shared__ __align__(16) float sWq[ED * ED];
    __shared__ __align__(16) float sWk[ED * ED];
    __shared__ __align__(16) float sWv[ED * ED];
    __shared__ __align__(16) float sWo[ED * ED];
    __shared__ float sbq[ED], sbk[ED], sbv[ED], sbo[ED];
    __shared__ __align__(16) float sW1[FF * ED];
    __shared__ __align__(16) float sW2[ED * FF];
    __shared__ float sb1[FF], sb2[ED];
    __shared__ float sblm[VO];
    // K / V exchange buffer; later reused (aliased) for the final-X token matrix.
    __shared__ __align__(16) float sKV[2 * BPB * SQ * KST];   // 26624 B

    const int tid = threadIdx.x;

    // ---- cooperative weight staging ----
    for (int i = tid; i < VO * ED; i += NTHREADS) sE[i] = embed[i];
    for (int i = tid; i < SQ * ED; i += NTHREADS) sPos[i] = pos[i];
    for (int i = tid; i < ED * ED; i += NTHREADS) {
        sWq[i] = Wq[i]; sWk[i] = Wk[i]; sWv[i] = Wv[i]; sWo[i] = Wo[i];
    }
    for (int i = tid; i < FF * ED; i += NTHREADS) { sW1[i] = W1[i]; sW2[i] = W2[i]; }
    if (tid < ED) {
        sbq[tid] = bq[tid]; sbk[tid] = bk[tid]; sbv[tid] = bv[tid];
        sbo[tid] = bo[tid]; sb2[tid] = b2[tid];
    }
    if (tid < FF) sb1[tid] = b1[tid];
    if (tid < VO) sblm[tid] = blm[tid];
    __syncthreads();

    const int bl = tid >> 3;   // local batch 0..31
    const int n  = tid & 7;    // token position 0..7
    const int b  = blockIdx.x * BPB + bl;

    // ---- embedding + positional ----
    const int tok = x[b * SQ + n];
    float X[ED];
    #pragma unroll
    for (int d = 0; d < ED; d++) X[d] = sE[tok * ED + d] + sPos[n * ED + d];

    // ---- pack X pairs for f32x2 matvecs ----
    u64 xp[ED / 2];
    #pragma unroll
    for (int j = 0; j < ED / 2; j++) xp[j] = pack2(X[2 * j], X[2 * j + 1]);

    // ---- Q, K, V projections (packed along D) ----
    float Q[ED];
    float* myK = &sKV[(bl * SQ + n) * KST];
    float* myV = &sKV[BPB * SQ * KST + (bl * SQ + n) * KST];
    #pragma unroll
    for (int i = 0; i < ED; i++) {
        const u64* wq = reinterpret_cast<const u64*>(sWq + i * ED);  // 48i bytes: 8B-aligned
        const u64* wk = reinterpret_cast<const u64*>(sWk + i * ED);
        const u64* wv = reinterpret_cast<const u64*>(sWv + i * ED);
        u64 aq = pack2(sbq[i], 0.f);
        u64 ak = pack2(sbk[i], 0.f);
        u64 av = pack2(sbv[i], 0.f);
        #pragma unroll
        for (int j = 0; j < ED / 2; j++) {
            aq = fma2(xp[j], wq[j], aq);
            ak = fma2(xp[j], wk[j], ak);
            av = fma2(xp[j], wv[j], av);
        }
        Q[i] = hsum2(aq); myK[i] = hsum2(ak); myV[i] = hsum2(av);
    }
    __syncwarp();   // K/V exchange is intra-warp (4 batches x 8 tokens per warp)

    // ---- causal attention over 8 tokens (scalar: K/V token stride 13 is 4B-aligned only) ----
    const float inv_scale = 0.28867513459481287f;  // 1/sqrt(12)
    float s[SQ];
    float smax = -1e30f;
    #pragma unroll
    for (int m = 0; m < SQ; m++) {
        const float* Km = &sKV[(bl * SQ + m) * KST];
        float acc = 0.f;
        #pragma unroll
        for (int d = 0; d < ED; d++) acc = fmaf(Q[d], Km[d], acc);
        acc *= inv_scale;
        s[m] = (m <= n) ? acc : -1e30f;
        smax = fmaxf(smax, s[m]);
    }
    float ssum = 0.f;
    #pragma unroll
    for (int m = 0; m < SQ; m++) {
        s[m] = (m <= n) ? __expf(s[m] - smax) : 0.f;
        ssum += s[m];
    }
    const float rsum = 1.f / ssum;
    float attn[ED];
    #pragma unroll
    for (int d = 0; d < ED; d++) attn[d] = 0.f;
    #pragma unroll
    for (int m = 0; m < SQ; m++) {
        const float w = s[m] * rsum;
        const float* Vm = &sKV[BPB * SQ * KST + (bl * SQ + m) * KST];
        #pragma unroll
        for (int d = 0; d < ED; d++) attn[d] = fmaf(w, Vm[d], attn[d]);
    }

    // ---- output projection (residual), packed ----
    u64 ap[ED / 2];
    #pragma unroll
    for (int j = 0; j < ED / 2; j++) ap[j] = pack2(attn[2 * j], attn[2 * j + 1]);
    #pragma unroll
    for (int i = 0; i < ED; i++) {
        const u64* wo = reinterpret_cast<const u64*>(sWo + i * ED);
        u64 a = pack2(sbo[i], 0.f);
        #pragma unroll
        for (int j = 0; j < ED / 2; j++) a = fma2(ap[j], wo[j], a);
        X[i] += hsum2(a);
    }

    // ---- FFN (residual), packed ----
    #pragma unroll
    for (int j = 0; j < ED / 2; j++) xp[j] = pack2(X[2 * j], X[2 * j + 1]);
    float h[FF];
    #pragma unroll
    for (int f = 0; f < FF; f++) {
        const u64* w1 = reinterpret_cast<const u64*>(sW1 + f * ED);   // 48f bytes: aligned
        u64 a = pack2(sb1[f], 0.f);
        #pragma unroll
        for (int j = 0; j < ED / 2; j++) a = fma2(xp[j], w1[j], a);
        h[f] = fmaxf(hsum2(a), 0.f);
    }
    u64 hp[FF / 2];
    #pragma unroll
    for (int j = 0; j < FF / 2; j++) hp[j] = pack2(h[2 * j], h[2 * j + 1]);
    #pragma unroll
    for (int i = 0; i < ED; i++) {
        const u64* w2 = reinterpret_cast<const u64*>(sW2 + i * FF);   // 96i bytes: aligned
        u64 a = pack2(sb2[i], 0.f);
        #pragma unroll
        for (int j = 0; j < FF / 2; j++) a = fma2(hp[j], w2[j], a);
        X[i] += hsum2(a);
    }

    // ---- park final X in smem (alias over dead K/V buffer) ----
    __syncthreads();                 // everyone done reading K/V
    float* sXf = sKV;                // [256][12], 48 B per token (16B aligned)
    #pragma unroll
    for (int d = 0; d < ED; d++) sXf[tid * ED + d] = X[d];
    __syncthreads();

    // ---- logits epilogue: thread owns one vocab row, sweeps 128 tokens ----
    const int v    = tid & (VO - 1);
    const int half = tid >> 7;       // tokens [half*128, half*128+128)
    const float bias = sblm[v];
    u64 ep[ED / 2];
    #pragma unroll
    for (int j = 0; j < ED / 2; j++)
        ep[j] = pack2(sE[v * ED + 2 * j], sE[v * ED + 2 * j + 1]);

    const size_t outbase = ((size_t)blockIdx.x * (BPB * SQ) + half * 128) * VO + v;
    #pragma unroll 4
    for (int k = 0; k < 128; k++) {
        const int t = half * 128 + k;
        const ulonglong2* xq = reinterpret_cast<const ulonglong2*>(sXf + t * ED);
        const ulonglong2 x0 = xq[0];   // broadcast LDS.128 (all lanes same t)
        const ulonglong2 x1 = xq[1];
        const ulonglong2 x2 = xq[2];
        u64 acc = pack2(bias, 0.f);
        acc = fma2(x0.x, ep[0], acc);
        acc = fma2(x0.y, ep[1], acc);
        acc = fma2(x1.x, ep[2], acc);
        acc = fma2(x1.y, ep[3], acc);
        acc = fma2(x2.x, ep[4], acc);
        acc = fma2(x2.y, ep[5], acc);
        out[outbase + (size_t)k * VO] = hsum2(acc);
    }
}

extern "C" void kernel_launch(void* const* d_in, const int* in_sizes, int n_in,
                              void* d_out, int out_size) {
    const int*   x     = (const int*)  d_in[0];
    const float* embed = (const float*)d_in[1];
    const float* pos   = (const float*)d_in[2];
    const float* Wq    = (const float*)d_in[3];
    const float* bq    = (const float*)d_in[4];
    const float* Wk    = (const float*)d_in[5];
    const float* bk    = (const float*)d_in[6];
    const float* Wv    = (const float*)d_in[7];
    const float* bv    = (const float*)d_in[8];
    const float* Wo    = (const float*)d_in[9];
    const float* bo    = (const float*)d_in[10];
    const float* W1    = (const float*)d_in[11];
    const float* b1    = (const float*)d_in[12];
    const float* W2    = (const float*)d_in[13];
    const float* b2    = (const float*)d_in[14];
    const float* blm   = (const float*)d_in[15];
    float* out = (float*)d_out;

    const int B = in_sizes[0] / SQ;          // 32768
    const int grid = B / BPB;                // 1024 blocks
    tiny_tf_kernel<<<grid, NTHREADS>>>(x, embed, pos,
                                       Wq, bq, Wk, bk, Wv, bv, Wo, bo,
                                       W1, b1, W2, b2, blm, out);
}

// round 3
// speedup vs baseline: 1.0577x; 1.0577x over previous
#include <cuda_runtime.h>

#define ED 12
#define FF 24
#define SQ 8
#define VO 128
#define BPB 32            // batch elements per block
#define NTHREADS 256
#define KST 14            // per-token K/V stride (floats): 8B-aligned, 2-way conflicts max

typedef unsigned long long u64;

__device__ __forceinline__ u64 pack2(float lo, float hi) {
    u64 r;
    asm("mov.b64 %0, {%1, %2};" : "=l"(r) : "f"(lo), "f"(hi));
    return r;
}
__device__ __forceinline__ void unpack2(u64 u, float& lo, float& hi) {
    asm("mov.b64 {%0, %1}, %2;" : "=f"(lo), "=f"(hi) : "l"(u));
}
__device__ __forceinline__ u64 fma2(u64 a, u64 b, u64 c) {
    u64 r;
    asm("fma.rn.f32x2 %0, %1, %2, %3;" : "=l"(r) : "l"(a), "l"(b), "l"(c));
    return r;
}
__device__ __forceinline__ float hsum2(u64 u) {
    float lo, hi; unpack2(u, lo, hi); return lo + hi;
}

// Precomputed tables: EWq|EWk|EWv [128][12] then PWq|PWk|PWv [8][12] (bias folded into PW)
__device__ __align__(16) float gTab[3 * VO * ED + 3 * SQ * ED];

__global__ void precompute_tables(const float* __restrict__ embed,
                                  const float* __restrict__ pos,
                                  const float* __restrict__ Wq, const float* __restrict__ bq,
                                  const float* __restrict__ Wk, const float* __restrict__ bk,
                                  const float* __restrict__ Wv, const float* __restrict__ bv)
{
    const int m = blockIdx.x;   // 0=q, 1=k, 2=v
    const float* W = (m == 0) ? Wq : (m == 1) ? Wk : Wv;
    const float* b = (m == 0) ? bq : (m == 1) ? bk : bv;
    float* EW = gTab + m * VO * ED;
    float* PW = gTab + 3 * VO * ED + m * SQ * ED;
    for (int idx = threadIdx.x; idx < VO * ED; idx += blockDim.x) {
        const int v = idx / ED, i = idx % ED;
        float a = 0.f;
        #pragma unroll
        for (int d = 0; d < ED; d++) a = fmaf(embed[v * ED + d], W[i * ED + d], a);
        EW[idx] = a;
    }
    for (int idx = threadIdx.x; idx < SQ * ED; idx += blockDim.x) {
        const int n = idx / ED, i = idx % ED;
        float a = b[i];
        #pragma unroll
        for (int d = 0; d < ED; d++) a = fmaf(pos[n * ED + d], W[i * ED + d], a);
        PW[idx] = a;
    }
}

__global__ __launch_bounds__(NTHREADS, 4)
void tiny_tf_kernel(const int* __restrict__ x,
                    const float* __restrict__ embed,
                    const float* __restrict__ pos,
                    const float* __restrict__ Wo, const float* __restrict__ bo,
                    const float* __restrict__ W1, const float* __restrict__ b1,
                    const float* __restrict__ W2, const float* __restrict__ b2,
                    const float* __restrict__ blm,
                    float* __restrict__ out)
{
    __shared__ __align__(16) float sPos[SQ * ED];
    __shared__ __align__(16) float sPW[3 * SQ * ED];     // bias-folded pos projections
    __shared__ __align__(16) float sWo[ED * ED];
    __shared__ __align__(16) float sW1[FF * ED];
    __shared__ __align__(16) float sW2[ED * FF];
    __shared__ float sbo[ED], sb1[FF], sb2[ED];
    __shared__ float sblm[VO];
    // K/V exchange buffer; later aliased for the final-X token matrix (needs 3072 floats)
    __shared__ __align__(16) float sKV[2 * BPB * SQ * KST];   // 7168 floats = 28672 B

    const int tid = threadIdx.x;
    const float* __restrict__ tEW = gTab;

    // ---- cooperative staging ----
    for (int i = tid; i < SQ * ED; i += NTHREADS) sPos[i] = pos[i];
    for (int i = tid; i < 3 * SQ * ED; i += NTHREADS) sPW[i] = gTab[3 * VO * ED + i];
    for (int i = tid; i < ED * ED; i += NTHREADS) sWo[i] = Wo[i];
    for (int i = tid; i < FF * ED; i += NTHREADS) { sW1[i] = W1[i]; sW2[i] = W2[i]; }
    if (tid < ED) { sbo[tid] = bo[tid]; sb2[tid] = b2[tid]; }
    if (tid < FF) sb1[tid] = b1[tid];
    if (tid < VO) sblm[tid] = blm[tid];
    __syncthreads();

    const int bl = tid >> 3;   // local batch 0..31
    const int n  = tid & 7;    // token position 0..7
    const int b  = blockIdx.x * BPB + bl;

    const int tok = x[b * SQ + n];

    // ---- X = E[tok] + pos[n]  (E row via LDG.128, L1-hot) ----
    float X[ED];
    {
        const float4* Er = reinterpret_cast<const float4*>(embed + tok * ED);
        const float4* Pr = reinterpret_cast<const float4*>(sPos + n * ED);
        #pragma unroll
        for (int q = 0; q < 3; q++) {
            const float4 e = Er[q], p = Pr[q];
            X[4 * q + 0] = e.x + p.x; X[4 * q + 1] = e.y + p.y;
            X[4 * q + 2] = e.z + p.z; X[4 * q + 3] = e.w + p.w;
        }
    }

    // ---- Q/K/V via tables: proj = EW[tok] + PW[n] ----
    u64 qp[ED / 2];
    float* myK = &sKV[(bl * SQ + n) * KST];
    float* myV = &sKV[BPB * SQ * KST + (bl * SQ + n) * KST];
    {
        const float4* EQ = reinterpret_cast<const float4*>(tEW + 0 * VO * ED + tok * ED);
        const float4* EK = reinterpret_cast<const float4*>(tEW + 1 * VO * ED + tok * ED);
        const float4* EV = reinterpret_cast<const float4*>(tEW + 2 * VO * ED + tok * ED);
        const float4* PQ = reinterpret_cast<const float4*>(sPW + 0 * SQ * ED + n * ED);
        const float4* PK = reinterpret_cast<const float4*>(sPW + 1 * SQ * ED + n * ED);
        const float4* PV = reinterpret_cast<const float4*>(sPW + 2 * SQ * ED + n * ED);
        u64* kd = reinterpret_cast<u64*>(myK);
        u64* vd = reinterpret_cast<u64*>(myV);
        #pragma unroll
        for (int q = 0; q < 3; q++) {
            const float4 eq = EQ[q], pq = PQ[q];
            qp[2 * q + 0] = pack2(eq.x + pq.x, eq.y + pq.y);
            qp[2 * q + 1] = pack2(eq.z + pq.z, eq.w + pq.w);
            const float4 ek = EK[q], pk = PK[q];
            kd[2 * q + 0] = pack2(ek.x + pk.x, ek.y + pk.y);
            kd[2 * q + 1] = pack2(ek.z + pk.z, ek.w + pk.w);
            const float4 ev = EV[q], pv = PV[q];
            vd[2 * q + 0] = pack2(ev.x + pv.x, ev.y + pv.y);
            vd[2 * q + 1] = pack2(ev.z + pv.z, ev.w + pv.w);
        }
    }
    __syncwarp();   // K/V exchange is intra-warp (4 batches x 8 tokens per warp)

    // ---- causal attention over 8 tokens (packed f32x2 dots) ----
    const float inv_scale = 0.28867513459481287f;  // 1/sqrt(12)
    float s[SQ];
    float smax = -1e30f;
    #pragma unroll
    for (int m = 0; m < SQ; m++) {
        const u64* Km = reinterpret_cast<const u64*>(&sKV[(bl * SQ + m) * KST]);
        u64 acc = pack2(0.f, 0.f);
        #pragma unroll
        for (int j = 0; j < ED / 2; j++) acc = fma2(qp[j], Km[j], acc);
        const float sc = hsum2(acc) * inv_scale;
        s[m] = (m <= n) ? sc : -1e30f;
        smax = fmaxf(smax, s[m]);
    }
    float ssum = 0.f;
    #pragma unroll
    for (int m = 0; m < SQ; m++) {
        s[m] = (m <= n) ? __expf(s[m] - smax) : 0.f;
        ssum += s[m];
    }
    const float rsum = 1.f / ssum;
    u64 ap[ED / 2];
    #pragma unroll
    for (int j = 0; j < ED / 2; j++) ap[j] = pack2(0.f, 0.f);
    #pragma unroll
    for (int m = 0; m < SQ; m++) {
        const float w = s[m] * rsum;
        const u64 w2 = pack2(w, w);
        const u64* Vm = reinterpret_cast<const u64*>(&sKV[BPB * SQ * KST + (bl * SQ + m) * KST]);
        #pragma unroll
        for (int j = 0; j < ED / 2; j++) ap[j] = fma2(w2, Vm[j], ap[j]);
    }

    // ---- output projection (residual), packed ----
    #pragma unroll
    for (int i = 0; i < ED; i++) {
        const u64* wo = reinterpret_cast<const u64*>(sWo + i * ED);
        u64 a = pack2(sbo[i], 0.f);
        #pragma unroll
        for (int j = 0; j < ED / 2; j++) a = fma2(ap[j], wo[j], a);
        X[i] += hsum2(a);
    }

    // ---- FFN (residual), packed ----
    u64 xp[ED / 2];
    #pragma unroll
    for (int j = 0; j < ED / 2; j++) xp[j] = pack2(X[2 * j], X[2 * j + 1]);
    float h[FF];
    #pragma unroll
    for (int f = 0; f < FF; f++) {
        const u64* w1 = reinterpret_cast<const u64*>(sW1 + f * ED);
        u64 a = pack2(sb1[f], 0.f);
        #pragma unroll
        for (int j = 0; j < ED / 2; j++) a = fma2(xp[j], w1[j], a);
        h[f] = fmaxf(hsum2(a), 0.f);
    }
    u64 hp[FF / 2];
    #pragma unroll
    for (int j = 0; j < FF / 2; j++) hp[j] = pack2(h[2 * j], h[2 * j + 1]);
    #pragma unroll
    for (int i = 0; i < ED; i++) {
        const u64* w2 = reinterpret_cast<const u64*>(sW2 + i * FF);
        u64 a = pack2(sb2[i], 0.f);
        #pragma unroll
        for (int j = 0; j < FF / 2; j++) a = fma2(hp[j], w2[j], a);
        X[i] += hsum2(a);
    }

    // ---- park final X in smem (alias over dead K/V buffer) ----
    __syncthreads();                 // everyone done reading K/V
    float* sXf = sKV;                // [256][12], 48 B per token, 16B-aligned rows
    {
        float4* xf = reinterpret_cast<float4*>(sXf) + tid * 3;
        xf[0] = make_float4(X[0], X[1], X[2], X[3]);
        xf[1] = make_float4(X[4], X[5], X[6], X[7]);
        xf[2] = make_float4(X[8], X[9], X[10], X[11]);
    }
    __syncthreads();

    // ---- logits epilogue: thread owns 2 adjacent vocab rows, sweeps 64 tokens ----
    const int v0   = (tid & 63) * 2;     // vocab pair (v0, v0+1)
    const int tseg = tid >> 6;           // token segment [tseg*64, tseg*64+64)
    const float bias0 = sblm[v0], bias1 = sblm[v0 + 1];
    u64 e0[ED / 2], e1[ED / 2];
    {
        const u64* E0 = reinterpret_cast<const u64*>(embed + v0 * ED);
        const u64* E1 = reinterpret_cast<const u64*>(embed + (v0 + 1) * ED);
        #pragma unroll
        for (int j = 0; j < ED / 2; j++) { e0[j] = E0[j]; e1[j] = E1[j]; }
    }

    const size_t rowbase = (size_t)blockIdx.x * (BPB * SQ) + tseg * 64;
    #pragma unroll 4
    for (int k = 0; k < 64; k++) {
        const int t = tseg * 64 + k;
        const ulonglong2* xq = reinterpret_cast<const ulonglong2*>(sXf + t * ED);
        const ulonglong2 x0 = xq[0];   // broadcast LDS.128 (t uniform per warp)
        const ulonglong2 x1 = xq[1];
        const ulonglong2 x2 = xq[2];
        u64 a0 = pack2(bias0, 0.f);
        u64 a1 = pack2(bias1, 0.f);
        a0 = fma2(x0.x, e0[0], a0);  a1 = fma2(x0.x, e1[0], a1);
        a0 = fma2(x0.y, e0[1], a0);  a1 = fma2(x0.y, e1[1], a1);
        a0 = fma2(x1.x, e0[2], a0);  a1 = fma2(x1.x, e1[2], a1);
        a0 = fma2(x1.y, e0[3], a0);  a1 = fma2(x1.y, e1[3], a1);
        a0 = fma2(x2.x, e0[4], a0);  a1 = fma2(x2.x, e1[4], a1);
        a0 = fma2(x2.y, e0[5], a0);  a1 = fma2(x2.y, e1[5], a1);
        float2 r;
        r.x = hsum2(a0);
        r.y = hsum2(a1);
        *reinterpret_cast<float2*>(out + (rowbase + k) * VO + v0) = r;
    }
}

extern "C" void kernel_launch(void* const* d_in, const int* in_sizes, int n_in,
                              void* d_out, int out_size) {
    const int*   x     = (const int*)  d_in[0];
    const float* embed = (const float*)d_in[1];
    const float* pos   = (const float*)d_in[2];
    const float* Wq    = (const float*)d_in[3];
    const float* bq    = (const float*)d_in[4];
    const float* Wk    = (const float*)d_in[5];
    const float* bk    = (const float*)d_in[6];
    const float* Wv    = (const float*)d_in[7];
    const float* bv    = (const float*)d_in[8];
    const float* Wo    = (const float*)d_in[9];
    const float* bo    = (const float*)d_in[10];
    const float* W1    = (const float*)d_in[11];
    const float* b1    = (const float*)d_in[12];
    const float* W2    = (const float*)d_in[13];
    const float* b2    = (const float*)d_in[14];
    const float* blm   = (const float*)d_in[15];
    float* out = (float*)d_out;

    precompute_tables<<<3, 512>>>(embed, pos, Wq, bq, Wk, bk, Wv, bv);

    const int B = in_sizes[0] / SQ;          // 32768
    const int grid = B / BPB;                // 1024 blocks
    tiny_tf_kernel<<<grid, NTHREADS>>>(x, embed, pos,
                                       Wo, bo, W1, b1, W2, b2, blm, out);
}